// round 1
// baseline (speedup 1.0000x reference)
#include <cuda_runtime.h>
#include <cuda_bf16.h>
#include <cstdint>

// ---------------------------------------------------------------------------
// vAttn: x[8,256,256,64] -> conv3x3 qkv -> attention over V per (b,t) ->
//        conv3x3 + residual.  All fp32.
// Layouts:
//   g_qkv : [b][t][v][192]  (ch 0..31 = q, 32..63 = k, 64..191 = v)
//   g_av  : [b][c1=128][v][t]  (NCHW, input to conv_o)
//   g_wt1 : [k=ic*9+r][oc] for 192 oc (q,k,v packed)
//   g_wt2 : [k][oc] for 256 oc
// ---------------------------------------------------------------------------

#define B_   8
#define V_   256
#define T_   64

__device__ float g_qkv[8ll * 64 * 256 * 192];   // 100.7 MB
__device__ float g_av [8ll * 128 * 256 * 64];   // 67.1 MB
__device__ float g_wt1[2304 * 192];
__device__ float g_wt2[1152 * 256];

// ---------------------------------------------------------------------------
// Weight packing: [oc][ic][3][3] -> [ic*9+r][oc]
// ---------------------------------------------------------------------------
__global__ void pack_qkv_w(const float* __restrict__ wq,
                           const float* __restrict__ wk,
                           const float* __restrict__ wv) {
    int id = blockIdx.x * blockDim.x + threadIdx.x;
    if (id >= 2304 * 192) return;
    int oc = id % 192, k = id / 192;
    int ic = k / 9, r = k % 9;
    float v;
    if (oc < 32)       v = wq[(oc * 256 + ic) * 9 + r];
    else if (oc < 64)  v = wk[((oc - 32) * 256 + ic) * 9 + r];
    else               v = wv[((oc - 64) * 256 + ic) * 9 + r];
    g_wt1[id] = v;
}

__global__ void pack_o_w(const float* __restrict__ wo) {
    int id = blockIdx.x * blockDim.x + threadIdx.x;
    if (id >= 1152 * 256) return;
    int oc = id % 256, k = id / 256;
    int ic = k / 9, r = k % 9;
    g_wt2[id] = wo[(oc * 128 + ic) * 9 + r];
}

// ---------------------------------------------------------------------------
// Implicit-GEMM conv3x3, stride 1, pad 1 over (V,T) spatial dims.
// Block tile: 64 oc x 128 positions (2 rows x 64 cols). 256 threads.
// Thread tile: 8 oc x 4 positions.  IC chunked by 8.
// TRANS=true : write [b][t][v][OCTOT]   (for qkv -> attention)
// TRANS=false: write NCHW; RESID adds resid + sigma*acc (final output)
// ---------------------------------------------------------------------------
template<int IC, int OCTOT, bool RESID, bool TRANS>
__global__ __launch_bounds__(256, 2)
void conv3x3_k(const float* __restrict__ in, const float* __restrict__ wt,
               float* __restrict__ out, const float* __restrict__ resid,
               const float* __restrict__ sigma) {
    __shared__ float sPatch[8][4][66];   // 8 ic x (2+2) rows x (64+2) cols
    __shared__ float sW[72][64];         // 8 ic * 9 taps x 64 oc

    const int tid  = threadIdx.x;
    const int lane = tid & 31;
    const int w    = tid >> 5;
    const int b    = blockIdx.z;
    const int y0   = blockIdx.y * 2;
    const int ocB  = blockIdx.x * 64;

    float acc[8][4];
#pragma unroll
    for (int m = 0; m < 8; m++)
#pragma unroll
        for (int j = 0; j < 4; j++) acc[m][j] = 0.f;

    for (int ic0 = 0; ic0 < IC; ic0 += 8) {
        __syncthreads();
        // input patch (with halo, zero padding)
        for (int idx = tid; idx < 2112; idx += 256) {
            int i = idx / 264, rem = idx % 264;
            int row = rem / 66, col = rem % 66;
            int gy = y0 - 1 + row, gx = col - 1;
            float v = 0.f;
            if (gy >= 0 && gy < V_ && gx >= 0 && gx < T_)
                v = in[(((size_t)b * IC + ic0 + i) * V_ + gy) * T_ + gx];
            sPatch[i][row][col] = v;
        }
        // weight chunk: k = ic0*9 + kk
        for (int idx = tid; idx < 4608; idx += 256) {
            int kk = idx >> 6, oc = idx & 63;
            sW[kk][oc] = wt[(size_t)(ic0 * 9 + kk) * OCTOT + ocB + oc];
        }
        __syncthreads();

        for (int i = 0; i < 8; ++i) {
#pragma unroll
            for (int r = 0; r < 9; ++r) {
                const int ky = r / 3, kx = r - ky * 3;
                float4 a0 = *(const float4*)&sW[i * 9 + r][w * 8];
                float4 a1 = *(const float4*)&sW[i * 9 + r][w * 8 + 4];
                float a[8] = {a0.x, a0.y, a0.z, a0.w, a1.x, a1.y, a1.z, a1.w};
                float bf[4];
                bf[0] = sPatch[i][ky    ][lane + kx];
                bf[1] = sPatch[i][ky    ][lane + kx + 32];
                bf[2] = sPatch[i][ky + 1][lane + kx];
                bf[3] = sPatch[i][ky + 1][lane + kx + 32];
#pragma unroll
                for (int m = 0; m < 8; m++)
#pragma unroll
                    for (int j = 0; j < 4; j++)
                        acc[m][j] = fmaf(a[m], bf[j], acc[m][j]);
            }
        }
    }

    if constexpr (TRANS) {
#pragma unroll
        for (int j = 0; j < 4; j++) {
            int y  = y0 + (j >> 1);
            int xx = (j & 1) * 32 + lane;
            size_t base = (((size_t)b * T_ + xx) * V_ + y) * OCTOT + ocB + w * 8;
            float4 v0 = make_float4(acc[0][j], acc[1][j], acc[2][j], acc[3][j]);
            float4 v1 = make_float4(acc[4][j], acc[5][j], acc[6][j], acc[7][j]);
            *(float4*)(out + base)     = v0;
            *(float4*)(out + base + 4) = v1;
        }
    } else {
        float sg = 0.f;
        if constexpr (RESID) sg = sigma[0];
#pragma unroll
        for (int m = 0; m < 8; m++) {
            int oc = ocB + w * 8 + m;
#pragma unroll
            for (int j = 0; j < 4; j++) {
                int y  = y0 + (j >> 1);
                int xx = (j & 1) * 32 + lane;
                size_t idx = (((size_t)b * OCTOT + oc) * V_ + y) * T_ + xx;
                float v = acc[m][j];
                if constexpr (RESID) v = resid[idx] + sg * v;
                out[idx] = v;
            }
        }
    }
}

// ---------------------------------------------------------------------------
// Attention: one block per (b,t) slice. 256 threads (8 warps).
// Whole slice in dynamic smem: Q[256][32], K[256][33] (padded), V[256][128],
// per-warp softmax row buffer [8][256]. Warp-per-query, lane owns 8 keys for
// scores and 4 output channels for AV.
// av written NCHW [b][c1][v][t].
// ---------------------------------------------------------------------------
#define ATTN_SMEM (51456 * 4)

__global__ __launch_bounds__(256)
void attn_kernel(const float* __restrict__ qkv, float* __restrict__ av) {
    extern __shared__ float sm[];
    float* Qs = sm;              // 256*32  = 8192 floats
    float* Ks = sm + 8192;       // 256*33  = 8448
    float* Vs = sm + 16640;      // 256*128 = 32768
    float* Pb = sm + 49408;      // 8*256   = 2048

    const int tid  = threadIdx.x;
    const int lane = tid & 31;
    const int w    = tid >> 5;
    const int t    = blockIdx.x;
    const int b    = blockIdx.y;

    // cooperative load of the slice [256 rows][192 ch]
    const float4* src4 = (const float4*)(qkv + ((size_t)(b * T_ + t)) * V_ * 192);
    for (int idx = tid; idx < 256 * 48; idx += 256) {
        int row = idx / 48, seg = idx % 48;
        float4 val = src4[row * 48 + seg];
        if (seg < 8) {
            *(float4*)&Qs[row * 32 + seg * 4] = val;
        } else if (seg < 16) {
            int c = seg * 4 - 32;
            Ks[row * 33 + c + 0] = val.x;
            Ks[row * 33 + c + 1] = val.y;
            Ks[row * 33 + c + 2] = val.z;
            Ks[row * 33 + c + 3] = val.w;
        } else {
            int c = seg * 4 - 64;
            *(float4*)&Vs[row * 128 + c] = val;
        }
    }
    __syncthreads();

    const int kbase = lane * 33;
    const float4* V4 = (const float4*)Vs;

    for (int qi = 0; qi < 32; ++qi) {
        const int qrow = w * 32 + qi;
        float s[8];
#pragma unroll
        for (int j = 0; j < 8; j++) s[j] = 0.f;
#pragma unroll
        for (int c = 0; c < 32; ++c) {
            float qc = Qs[qrow * 32 + c];  // broadcast
#pragma unroll
            for (int j = 0; j < 8; j++)
                s[j] = fmaf(qc, Ks[kbase + j * 1056 + c], s[j]);
        }
        // softmax over all 256 keys of this query (warp-wide)
        float mx = s[0];
#pragma unroll
        for (int j = 1; j < 8; j++) mx = fmaxf(mx, s[j]);
#pragma unroll
        for (int o = 16; o >= 1; o >>= 1)
            mx = fmaxf(mx, __shfl_xor_sync(0xffffffffu, mx, o));
        float l = 0.f, p[8];
#pragma unroll
        for (int j = 0; j < 8; j++) { p[j] = __expf(s[j] - mx); l += p[j]; }
#pragma unroll
        for (int o = 16; o >= 1; o >>= 1)
            l += __shfl_xor_sync(0xffffffffu, l, o);
        float rinv = 1.0f / l;
#pragma unroll
        for (int j = 0; j < 8; j++) Pb[w * 256 + j * 32 + lane] = p[j];
        __syncwarp();

        float4 o4 = make_float4(0.f, 0.f, 0.f, 0.f);
#pragma unroll 8
        for (int u = 0; u < 256; ++u) {
            float pu  = Pb[w * 256 + u];     // broadcast
            float4 vv = V4[u * 32 + lane];   // conflict-free LDS.128
            o4.x = fmaf(pu, vv.x, o4.x);
            o4.y = fmaf(pu, vv.y, o4.y);
            o4.z = fmaf(pu, vv.z, o4.z);
            o4.w = fmaf(pu, vv.w, o4.w);
        }
        o4.x *= rinv; o4.y *= rinv; o4.z *= rinv; o4.w *= rinv;

        size_t ob = (((size_t)b * 128 + lane * 4) * V_ + qrow) * T_ + t;
        av[ob]             = o4.x;
        av[ob + 1 * 16384] = o4.y;
        av[ob + 2 * 16384] = o4.z;
        av[ob + 3 * 16384] = o4.w;
        __syncwarp();
    }
}

// ---------------------------------------------------------------------------
extern "C" void kernel_launch(void* const* d_in, const int* in_sizes, int n_in,
                              void* d_out, int out_size) {
    const float* x     = (const float*)d_in[0];
    const float* wq    = (const float*)d_in[1];
    const float* wk    = (const float*)d_in[2];
    const float* wv    = (const float*)d_in[3];
    const float* wo    = (const float*)d_in[4];
    const float* sigma = (const float*)d_in[5];
    float* out = (float*)d_out;

    float *qkv, *av;
    cudaGetSymbolAddress((void**)&qkv, g_qkv);
    cudaGetSymbolAddress((void**)&av,  g_av);

    pack_qkv_w<<<(2304 * 192 + 255) / 256, 256>>>(wq, wk, wv);
    pack_o_w  <<<(1152 * 256 + 255) / 256, 256>>>(wo);

    float *wt1, *wt2;
    cudaGetSymbolAddress((void**)&wt1, g_wt1);
    cudaGetSymbolAddress((void**)&wt2, g_wt2);

    // conv qkv: 192 out ch, IC=256, write transposed [b][t][v][192]
    conv3x3_k<256, 192, false, true><<<dim3(3, 128, 8), 256>>>(
        x, wt1, qkv, nullptr, nullptr);

    cudaFuncSetAttribute(attn_kernel,
                         cudaFuncAttributeMaxDynamicSharedMemorySize, ATTN_SMEM);
    attn_kernel<<<dim3(T_, B_), 256, ATTN_SMEM>>>(qkv, av);

    // conv o: 256 out ch, IC=128, NCHW + residual + sigma
    conv3x3_k<128, 256, true, false><<<dim3(4, 128, 8), 256>>>(
        av, wt2, out, x, sigma);
}

// round 2
// speedup vs baseline: 1.0015x; 1.0015x over previous
#include <cuda_runtime.h>
#include <cuda_bf16.h>
#include <cstdint>

// ---------------------------------------------------------------------------
// vAttn: x[8,256,256,64] -> conv3x3 qkv -> attention over V per (b,t) ->
//        conv3x3 + residual.  All fp32.
// Layouts:
//   g_qkv : [b][t][v][192]  (ch 0..31 = q, 32..63 = k, 64..191 = v)
//   g_av  : [b][c1=128][v][t]  (NCHW, input to conv_o)
//   g_wt1 : [k=ic*9+r][oc] for 192 oc (q,k,v packed)
//   g_wt2 : [k][oc] for 256 oc
// ---------------------------------------------------------------------------

#define B_   8
#define V_   256
#define T_   64

__device__ float g_qkv[8ll * 64 * 256 * 192];   // 100.7 MB
__device__ float g_av [8ll * 128 * 256 * 64];   // 67.1 MB
__device__ float g_wt1[2304 * 192];
__device__ float g_wt2[1152 * 256];

// ---------------------------------------------------------------------------
// Weight packing: [oc][ic][3][3] -> [ic*9+r][oc]
// ---------------------------------------------------------------------------
__global__ void pack_qkv_w(const float* __restrict__ wq,
                           const float* __restrict__ wk,
                           const float* __restrict__ wv) {
    int id = blockIdx.x * blockDim.x + threadIdx.x;
    if (id >= 2304 * 192) return;
    int oc = id % 192, k = id / 192;
    int ic = k / 9, r = k % 9;
    float v;
    if (oc < 32)       v = wq[(oc * 256 + ic) * 9 + r];
    else if (oc < 64)  v = wk[((oc - 32) * 256 + ic) * 9 + r];
    else               v = wv[((oc - 64) * 256 + ic) * 9 + r];
    g_wt1[id] = v;
}

__global__ void pack_o_w(const float* __restrict__ wo) {
    int id = blockIdx.x * blockDim.x + threadIdx.x;
    if (id >= 1152 * 256) return;
    int oc = id % 256, k = id / 256;
    int ic = k / 9, r = k % 9;
    g_wt2[id] = wo[(oc * 128 + ic) * 9 + r];
}

// ---------------------------------------------------------------------------
// Implicit-GEMM conv3x3, stride 1, pad 1 over (V,T) spatial dims.
// Block tile: 64 oc x 128 positions (2 rows x 64 cols). 256 threads.
// Thread tile: 8 oc x 4 positions.  IC chunked by 8.
// TRANS=true : write [b][t][v][OCTOT]   (for qkv -> attention)
// TRANS=false: write NCHW; RESID adds resid + sigma*acc (final output)
// ---------------------------------------------------------------------------
template<int IC, int OCTOT, bool RESID, bool TRANS>
__global__ __launch_bounds__(256, 2)
void conv3x3_k(const float* __restrict__ in, const float* __restrict__ wt,
               float* __restrict__ out, const float* __restrict__ resid,
               const float* __restrict__ sigma) {
    __shared__ float sPatch[8][4][66];   // 8 ic x (2+2) rows x (64+2) cols
    __shared__ float sW[72][64];         // 8 ic * 9 taps x 64 oc

    const int tid  = threadIdx.x;
    const int lane = tid & 31;
    const int w    = tid >> 5;
    const int b    = blockIdx.z;
    const int y0   = blockIdx.y * 2;
    const int ocB  = blockIdx.x * 64;

    float acc[8][4];
#pragma unroll
    for (int m = 0; m < 8; m++)
#pragma unroll
        for (int j = 0; j < 4; j++) acc[m][j] = 0.f;

    for (int ic0 = 0; ic0 < IC; ic0 += 8) {
        __syncthreads();
        // input patch (with halo, zero padding)
        for (int idx = tid; idx < 2112; idx += 256) {
            int i = idx / 264, rem = idx % 264;
            int row = rem / 66, col = rem % 66;
            int gy = y0 - 1 + row, gx = col - 1;
            float v = 0.f;
            if (gy >= 0 && gy < V_ && gx >= 0 && gx < T_)
                v = in[(((size_t)b * IC + ic0 + i) * V_ + gy) * T_ + gx];
            sPatch[i][row][col] = v;
        }
        // weight chunk: k = ic0*9 + kk
        for (int idx = tid; idx < 4608; idx += 256) {
            int kk = idx >> 6, oc = idx & 63;
            sW[kk][oc] = wt[(size_t)(ic0 * 9 + kk) * OCTOT + ocB + oc];
        }
        __syncthreads();

        for (int i = 0; i < 8; ++i) {
#pragma unroll
            for (int r = 0; r < 9; ++r) {
                const int ky = r / 3, kx = r - ky * 3;
                float4 a0 = *(const float4*)&sW[i * 9 + r][w * 8];
                float4 a1 = *(const float4*)&sW[i * 9 + r][w * 8 + 4];
                float a[8] = {a0.x, a0.y, a0.z, a0.w, a1.x, a1.y, a1.z, a1.w};
                float bf[4];
                bf[0] = sPatch[i][ky    ][lane + kx];
                bf[1] = sPatch[i][ky    ][lane + kx + 32];
                bf[2] = sPatch[i][ky + 1][lane + kx];
                bf[3] = sPatch[i][ky + 1][lane + kx + 32];
#pragma unroll
                for (int m = 0; m < 8; m++)
#pragma unroll
                    for (int j = 0; j < 4; j++)
                        acc[m][j] = fmaf(a[m], bf[j], acc[m][j]);
            }
        }
    }

    if constexpr (TRANS) {
#pragma unroll
        for (int j = 0; j < 4; j++) {
            int y  = y0 + (j >> 1);
            int xx = (j & 1) * 32 + lane;
            size_t base = (((size_t)b * T_ + xx) * V_ + y) * OCTOT + ocB + w * 8;
            float4 v0 = make_float4(acc[0][j], acc[1][j], acc[2][j], acc[3][j]);
            float4 v1 = make_float4(acc[4][j], acc[5][j], acc[6][j], acc[7][j]);
            *(float4*)(out + base)     = v0;
            *(float4*)(out + base + 4) = v1;
        }
    } else {
        float sg = 0.f;
        if constexpr (RESID) sg = sigma[0];
#pragma unroll
        for (int m = 0; m < 8; m++) {
            int oc = ocB + w * 8 + m;
#pragma unroll
            for (int j = 0; j < 4; j++) {
                int y  = y0 + (j >> 1);
                int xx = (j & 1) * 32 + lane;
                size_t idx = (((size_t)b * OCTOT + oc) * V_ + y) * T_ + xx;
                float v = acc[m][j];
                if constexpr (RESID) v = resid[idx] + sg * v;
                out[idx] = v;
            }
        }
    }
}

// ---------------------------------------------------------------------------
// Attention: one block per (b,t) slice. 256 threads (8 warps).
// Whole slice in dynamic smem: Q[256][32], K[256][33] (padded), V[256][128],
// per-warp softmax row buffer [8][256]. Warp-per-query, lane owns 8 keys for
// scores and 4 output channels for AV.
// av written NCHW [b][c1][v][t].
// ---------------------------------------------------------------------------
#define ATTN_SMEM (51456 * 4)

__global__ __launch_bounds__(256)
void attn_kernel(const float* __restrict__ qkv, float* __restrict__ av) {
    extern __shared__ float sm[];
    float* Qs = sm;              // 256*32  = 8192 floats
    float* Ks = sm + 8192;       // 256*33  = 8448
    float* Vs = sm + 16640;      // 256*128 = 32768
    float* Pb = sm + 49408;      // 8*256   = 2048

    const int tid  = threadIdx.x;
    const int lane = tid & 31;
    const int w    = tid >> 5;
    const int t    = blockIdx.x;
    const int b    = blockIdx.y;

    // cooperative load of the slice [256 rows][192 ch]
    const float4* src4 = (const float4*)(qkv + ((size_t)(b * T_ + t)) * V_ * 192);
    for (int idx = tid; idx < 256 * 48; idx += 256) {
        int row = idx / 48, seg = idx % 48;
        float4 val = src4[row * 48 + seg];
        if (seg < 8) {
            *(float4*)&Qs[row * 32 + seg * 4] = val;
        } else if (seg < 16) {
            int c = seg * 4 - 32;
            Ks[row * 33 + c + 0] = val.x;
            Ks[row * 33 + c + 1] = val.y;
            Ks[row * 33 + c + 2] = val.z;
            Ks[row * 33 + c + 3] = val.w;
        } else {
            int c = seg * 4 - 64;
            *(float4*)&Vs[row * 128 + c] = val;
        }
    }
    __syncthreads();

    const int kbase = lane * 33;
    const float4* V4 = (const float4*)Vs;

    for (int qi = 0; qi < 32; ++qi) {
        const int qrow = w * 32 + qi;
        float s[8];
#pragma unroll
        for (int j = 0; j < 8; j++) s[j] = 0.f;
#pragma unroll
        for (int c = 0; c < 32; ++c) {
            float qc = Qs[qrow * 32 + c];  // broadcast
#pragma unroll
            for (int j = 0; j < 8; j++)
                s[j] = fmaf(qc, Ks[kbase + j * 1056 + c], s[j]);
        }
        // softmax over all 256 keys of this query (warp-wide)
        float mx = s[0];
#pragma unroll
        for (int j = 1; j < 8; j++) mx = fmaxf(mx, s[j]);
#pragma unroll
        for (int o = 16; o >= 1; o >>= 1)
            mx = fmaxf(mx, __shfl_xor_sync(0xffffffffu, mx, o));
        float l = 0.f, p[8];
#pragma unroll
        for (int j = 0; j < 8; j++) { p[j] = __expf(s[j] - mx); l += p[j]; }
#pragma unroll
        for (int o = 16; o >= 1; o >>= 1)
            l += __shfl_xor_sync(0xffffffffu, l, o);
        float rinv = 1.0f / l;
#pragma unroll
        for (int j = 0; j < 8; j++) Pb[w * 256 + j * 32 + lane] = p[j];
        __syncwarp();

        float4 o4 = make_float4(0.f, 0.f, 0.f, 0.f);
#pragma unroll 8
        for (int u = 0; u < 256; ++u) {
            float pu  = Pb[w * 256 + u];     // broadcast
            float4 vv = V4[u * 32 + lane];   // conflict-free LDS.128
            o4.x = fmaf(pu, vv.x, o4.x);
            o4.y = fmaf(pu, vv.y, o4.y);
            o4.z = fmaf(pu, vv.z, o4.z);
            o4.w = fmaf(pu, vv.w, o4.w);
        }
        o4.x *= rinv; o4.y *= rinv; o4.z *= rinv; o4.w *= rinv;

        size_t ob = (((size_t)b * 128 + lane * 4) * V_ + qrow) * T_ + t;
        av[ob]             = o4.x;
        av[ob + 1 * 16384] = o4.y;
        av[ob + 2 * 16384] = o4.z;
        av[ob + 3 * 16384] = o4.w;
        __syncwarp();
    }
}

// ---------------------------------------------------------------------------
extern "C" void kernel_launch(void* const* d_in, const int* in_sizes, int n_in,
                              void* d_out, int out_size) {
    const float* x     = (const float*)d_in[0];
    const float* wq    = (const float*)d_in[1];
    const float* wk    = (const float*)d_in[2];
    const float* wv    = (const float*)d_in[3];
    const float* wo    = (const float*)d_in[4];
    const float* sigma = (const float*)d_in[5];
    float* out = (float*)d_out;

    float *qkv, *av;
    cudaGetSymbolAddress((void**)&qkv, g_qkv);
    cudaGetSymbolAddress((void**)&av,  g_av);

    pack_qkv_w<<<(2304 * 192 + 255) / 256, 256>>>(wq, wk, wv);
    pack_o_w  <<<(1152 * 256 + 255) / 256, 256>>>(wo);

    float *wt1, *wt2;
    cudaGetSymbolAddress((void**)&wt1, g_wt1);
    cudaGetSymbolAddress((void**)&wt2, g_wt2);

    // conv qkv: 192 out ch, IC=256, write transposed [b][t][v][192]
    conv3x3_k<256, 192, false, true><<<dim3(3, 128, 8), 256>>>(
        x, wt1, qkv, nullptr, nullptr);

    cudaFuncSetAttribute(attn_kernel,
                         cudaFuncAttributeMaxDynamicSharedMemorySize, ATTN_SMEM);
    attn_kernel<<<dim3(T_, B_), 256, ATTN_SMEM>>>(qkv, av);

    // conv o: 256 out ch, IC=128, NCHW + residual + sigma
    conv3x3_k<128, 256, true, false><<<dim3(4, 128, 8), 256>>>(
        av, wt2, out, x, sigma);
}

// round 4
// speedup vs baseline: 2.5825x; 2.5786x over previous
#include <cuda_runtime.h>
#include <cuda_bf16.h>
#include <cstdint>

#define B_   8
#define V_   256
#define T_   64

// ---------------------------------------------------------------------------
// Global scratch
// ---------------------------------------------------------------------------
__device__ float g_qkv[8ll * 64 * 256 * 192];                      // [b][t][v][192] fp32
__device__ __nv_bfloat16 g_xh[8ll * 256 * 64 * 256];               // [b][v][t][256ic]
__device__ __nv_bfloat16 g_xl[8ll * 256 * 64 * 256];
__device__ __nv_bfloat16 g_avh[8ll * 256 * 64 * 128];              // [b][v][t][128ic]
__device__ __nv_bfloat16 g_avl[8ll * 256 * 64 * 128];
__device__ __nv_bfloat16 g_w1h[192 * 2304], g_w1l[192 * 2304];     // [oc][chunk][tap][16]
__device__ __nv_bfloat16 g_w2h[256 * 1152], g_w2l[256 * 1152];

// ---------------------------------------------------------------------------
// Helpers
// ---------------------------------------------------------------------------
__device__ __forceinline__ uint32_t smem_u32(const void* p) {
    return (uint32_t)__cvta_generic_to_shared(p);
}
__device__ __forceinline__ uint32_t pack2bf(float f0, float f1) {
    __nv_bfloat162 h = __floats2bfloat162_rn(f0, f1);   // .x=f0(lo16) .y=f1(hi16)
    return *(uint32_t*)&h;
}

#define LDMX4(r, a) \
    asm volatile("ldmatrix.sync.aligned.m8n8.x4.shared.b16 {%0,%1,%2,%3},[%4];" \
        : "=r"((r)[0]), "=r"((r)[1]), "=r"((r)[2]), "=r"((r)[3]) : "r"(a))
#define LDMX2(r, a) \
    asm volatile("ldmatrix.sync.aligned.m8n8.x2.shared.b16 {%0,%1},[%2];" \
        : "=r"((r)[0]), "=r"((r)[1]) : "r"(a))

__device__ __forceinline__ void mma16816(float* c, const uint32_t* a, const uint32_t* b) {
    asm volatile(
        "mma.sync.aligned.m16n8k16.row.col.f32.bf16.bf16.f32 "
        "{%0,%1,%2,%3},{%4,%5,%6,%7},{%8,%9},{%0,%1,%2,%3};"
        : "+f"(c[0]), "+f"(c[1]), "+f"(c[2]), "+f"(c[3])
        : "r"(a[0]), "r"(a[1]), "r"(a[2]), "r"(a[3]), "r"(b[0]), "r"(b[1]));
}

// ---------------------------------------------------------------------------
// split_x: x NCHW fp32 -> [b][y][t][256ic] bf16 hi/lo (ic contiguous)
// ---------------------------------------------------------------------------
__global__ void split_x_k(const float* __restrict__ x,
                          __nv_bfloat16* __restrict__ xh,
                          __nv_bfloat16* __restrict__ xl) {
    extern __shared__ float s[];               // [256 ic][65]
    const int y = blockIdx.x, b = blockIdx.y, tid = threadIdx.x;
    for (int r = 0; r < 64; r++) {
        int idx = r * 256 + tid, ic = idx >> 6, t = idx & 63;
        s[ic * 65 + t] = x[(((size_t)b * 256 + ic) * 256 + y) * 64 + t];
    }
    __syncthreads();
    size_t ob = ((size_t)(b * 256 + y)) * 64 * 256;
    for (int r = 0; r < 32; r++) {
        int idx = r * 512 + tid * 2, t = idx >> 8, ic = idx & 255;
        float f0 = s[ic * 65 + t], f1 = s[(ic + 1) * 65 + t];
        uint32_t hp = pack2bf(f0, f1);
        float h0 = __uint_as_float(hp << 16);
        float h1 = __uint_as_float(hp & 0xFFFF0000u);
        uint32_t lp = pack2bf(f0 - h0, f1 - h1);
        *(uint32_t*)(xh + ob + (size_t)t * 256 + ic) = hp;
        *(uint32_t*)(xl + ob + (size_t)t * 256 + ic) = lp;
    }
}

// ---------------------------------------------------------------------------
// Weight packing: w[oc][ic][3][3] -> [oc][icchunk][tap][16ic] hi/lo
// ---------------------------------------------------------------------------
__global__ void pack_w1_k(const float* __restrict__ wq,
                          const float* __restrict__ wk,
                          const float* __restrict__ wv) {
    int id = blockIdx.x * blockDim.x + threadIdx.x;
    if (id >= 192 * 2304) return;
    int oc = id / 2304, kp = id % 2304;
    int chunk = kp / 144, rem = kp % 144, tap = rem / 16, i = rem & 15;
    int ic = chunk * 16 + i;
    float v;
    if (oc < 32)       v = wq[(oc * 256 + ic) * 9 + tap];
    else if (oc < 64)  v = wk[((oc - 32) * 256 + ic) * 9 + tap];
    else               v = wv[((oc - 64) * 256 + ic) * 9 + tap];
    __nv_bfloat16 h = __float2bfloat16(v);
    g_w1h[id] = h;
    g_w1l[id] = __float2bfloat16(v - __bfloat162float(h));
}

__global__ void pack_w2_k(const float* __restrict__ wo) {
    int id = blockIdx.x * blockDim.x + threadIdx.x;
    if (id >= 256 * 1152) return;
    int oc = id / 1152, kp = id % 1152;
    int chunk = kp / 144, rem = kp % 144, tap = rem / 16, i = rem & 15;
    int ic = chunk * 16 + i;
    float v = wo[(oc * 128 + ic) * 9 + tap];
    __nv_bfloat16 h = __float2bfloat16(v);
    g_w2h[id] = h;
    g_w2l[id] = __float2bfloat16(v - __bfloat162float(h));
}

// ---------------------------------------------------------------------------
// conv3x3 via mma.sync bf16 (hi/lo split, 3 passes), tap-major K ordering.
// CTA: M=256 positions (4 V-rows x 64 T) x N=64 oc. 256 thr, warp grid 4x2.
// Input: pre-split bf16, ic-contiguous [b][v][t][IC].
// Patch smem: [6 rows][68 cols][pixel stride 48B, 16 ic x bf16 used].
// B smem: [64 oc][row stride 304B: 9 taps x 16 ic].
// ---------------------------------------------------------------------------
#define CONV_SMEM 78080

template<int ICC, int OCTOT, bool RESID, bool TRANS>
__global__ __launch_bounds__(256, 2)
void conv_mma(const __nv_bfloat16* __restrict__ inh,
              const __nv_bfloat16* __restrict__ inl,
              const __nv_bfloat16* __restrict__ wh,
              const __nv_bfloat16* __restrict__ wl,
              float* __restrict__ out,
              const float* __restrict__ resid,
              const float* __restrict__ sigma) {
    constexpr int IC  = ICC * 16;
    constexpr int ALo = 19584;            // lo patch offset
    constexpr int BHo = 39168;            // B hi offset
    extern __shared__ char sm[];

    const int tid  = threadIdx.x;
    const int lane = tid & 31;
    const int w    = tid >> 5;
    const int ocB  = blockIdx.x * 64;
    const int y0   = blockIdx.y * 4;
    const int b    = blockIdx.z;
    const int m0   = (w & 3) * 64;
    const int n0   = (w >> 2) * 32;
    const uint32_t sa = smem_u32(sm);
    const uint32_t sb = sa + BHo;

    float acc[4][4][4];
#pragma unroll
    for (int i = 0; i < 4; i++)
#pragma unroll
        for (int j = 0; j < 4; j++)
#pragma unroll
            for (int e = 0; e < 4; e++) acc[i][j][e] = 0.f;

    for (int c = 0; c < ICC; ++c) {
        __syncthreads();
        const int ic0 = c * 16;
        // ---- stage A patch: 6x66 pixels, 16 ic each, hi+lo ----
        for (int i = tid; i < 792; i += 256) {
            int half = i & 1, p = i >> 1;
            int row = p / 66, col = p - row * 66;
            int gy = y0 + row - 1, gt = col - 1;
            float4 v0 = make_float4(0.f, 0.f, 0.f, 0.f), v1 = v0;
            if ((unsigned)gy < 256u && (unsigned)gt < 64u) {
                const float4* src = (const float4*)((half ? inl : inh)
                    + ((size_t)((b * 256 + gy) * 64 + gt)) * IC + ic0);
                v0 = src[0]; v1 = src[1];
            }
            char* dst = sm + half * ALo + (row * 68 + col) * 48;
            *(float4*)dst        = v0;
            *(float4*)(dst + 16) = v1;
        }
        // ---- stage B: 64 oc x 144 bf16 (9 taps x 16 ic), hi+lo ----
        for (int i = tid; i < 2304; i += 256) {
            int half = i >= 1152;
            int r = half ? i - 1152 : i;
            int n = r / 18, seg = r - n * 18;
            const float4* src = (const float4*)((half ? wl : wh)
                + ((size_t)(ocB + n) * ICC + c) * 144 + seg * 8);
            *(float4*)(sm + BHo + half * 19456 + n * 304 + seg * 16) = src[0];
        }
        __syncthreads();

        const int l16 = lane & 15;
#pragma unroll
        for (int tap = 0; tap < 9; ++tap) {
            const int ky = tap / 3, kx = tap - ky * 3;
            uint32_t bh[4][2], bl[4][2];
#pragma unroll
            for (int nt = 0; nt < 4; ++nt) {
                uint32_t ad = sb + (n0 + nt * 8 + (l16 & 7)) * 304
                            + tap * 32 + (l16 >> 3) * 16;
                LDMX2(bh[nt], ad);
                LDMX2(bl[nt], ad + 19456);
            }
#pragma unroll
            for (int mt = 0; mt < 4; ++mt) {
                int mrow = m0 + mt * 16 + l16;
                int rp = (mrow >> 6) + ky, cp = (mrow & 63) + kx;
                uint32_t ad = sa + (rp * 68 + cp) * 48 + (lane >> 4) * 16;
                uint32_t ah[4], al[4];
                LDMX4(ah, ad);
                LDMX4(al, ad + ALo);
#pragma unroll
                for (int nt = 0; nt < 4; ++nt) {
                    mma16816(acc[mt][nt], ah, bh[nt]);
                    mma16816(acc[mt][nt], ah, bl[nt]);
                    mma16816(acc[mt][nt], al, bh[nt]);
                }
            }
        }
    }

    // ---- epilogue ----
    const int r0l = lane >> 2, c0l = (lane & 3) * 2;
    if constexpr (TRANS) {
#pragma unroll
        for (int mt = 0; mt < 4; ++mt)
#pragma unroll
            for (int nt = 0; nt < 4; ++nt) {
                int oc = ocB + n0 + nt * 8 + c0l;
#pragma unroll
                for (int h = 0; h < 2; ++h) {
                    int m = m0 + mt * 16 + r0l + h * 8;
                    int v = y0 + (m >> 6), t = m & 63;
                    *(float2*)(out + ((size_t)((b * 64 + t) * 256 + v)) * OCTOT + oc)
                        = make_float2(acc[mt][nt][h * 2], acc[mt][nt][h * 2 + 1]);
                }
            }
    } else {
        float sg = sigma[0];
#pragma unroll
        for (int mt = 0; mt < 4; ++mt)
#pragma unroll
            for (int nt = 0; nt < 4; ++nt)
#pragma unroll
                for (int h = 0; h < 2; ++h) {
                    int m = m0 + mt * 16 + r0l + h * 8;
                    int v = y0 + (m >> 6), t = m & 63;
#pragma unroll
                    for (int e = 0; e < 2; ++e) {
                        int oc = ocB + n0 + nt * 8 + c0l + e;
                        size_t idx = (((size_t)b * OCTOT + oc) * 256 + v) * 64 + t;
                        out[idx] = resid[idx] + sg * acc[mt][nt][h * 2 + e];
                    }
                }
    }
}

// ---------------------------------------------------------------------------
// Attention (fp32 math): one block per (b,t), 512 thr (16 warps), slice in smem.
// Writes av directly as split bf16, ic-contiguous [b][v][t][128].
// ---------------------------------------------------------------------------
#define ATTN_SMEM (53504 * 4)

__global__ __launch_bounds__(512)
void attn_kernel(const float* __restrict__ qkv,
                 __nv_bfloat16* __restrict__ avh,
                 __nv_bfloat16* __restrict__ avl) {
    extern __shared__ float smf[];
    float* Qs = smf;              // 256*32
    float* Ks = smf + 8192;       // 256*33
    float* Vs = smf + 16640;      // 256*128
    float* Pb = smf + 49408;      // 16*256

    const int tid  = threadIdx.x;
    const int lane = tid & 31;
    const int w    = tid >> 5;
    const int t    = blockIdx.x;
    const int b    = blockIdx.y;

    const float4* src4 = (const float4*)(qkv + ((size_t)(b * T_ + t)) * V_ * 192);
    for (int idx = tid; idx < 256 * 48; idx += 512) {
        int row = idx / 48, seg = idx % 48;
        float4 val = src4[row * 48 + seg];
        if (seg < 8) {
            *(float4*)&Qs[row * 32 + seg * 4] = val;
        } else if (seg < 16) {
            int c = seg * 4 - 32;
            Ks[row * 33 + c + 0] = val.x;
            Ks[row * 33 + c + 1] = val.y;
            Ks[row * 33 + c + 2] = val.z;
            Ks[row * 33 + c + 3] = val.w;
        } else {
            int c = seg * 4 - 64;
            *(float4*)&Vs[row * 128 + c] = val;
        }
    }
    __syncthreads();

    const int kbase = lane * 33;
    const float4* V4 = (const float4*)Vs;

    for (int qi = 0; qi < 16; ++qi) {
        const int qrow = w * 16 + qi;
        float s[8];
#pragma unroll
        for (int j = 0; j < 8; j++) s[j] = 0.f;
#pragma unroll
        for (int c = 0; c < 32; ++c) {
            float qc = Qs[qrow * 32 + c];
#pragma unroll
            for (int j = 0; j < 8; j++)
                s[j] = fmaf(qc, Ks[kbase + j * 1056 + c], s[j]);
        }
        float mx = s[0];
#pragma unroll
        for (int j = 1; j < 8; j++) mx = fmaxf(mx, s[j]);
#pragma unroll
        for (int o = 16; o >= 1; o >>= 1)
            mx = fmaxf(mx, __shfl_xor_sync(0xffffffffu, mx, o));
        float l = 0.f, p[8];
#pragma unroll
        for (int j = 0; j < 8; j++) { p[j] = __expf(s[j] - mx); l += p[j]; }
#pragma unroll
        for (int o = 16; o >= 1; o >>= 1)
            l += __shfl_xor_sync(0xffffffffu, l, o);
        float rinv = 1.0f / l;
#pragma unroll
        for (int j = 0; j < 8; j++) Pb[w * 256 + j * 32 + lane] = p[j];
        __syncwarp();

        float4 o4 = make_float4(0.f, 0.f, 0.f, 0.f);
#pragma unroll 8
        for (int u = 0; u < 256; ++u) {
            float pu  = Pb[w * 256 + u];
            float4 vv = V4[u * 32 + lane];
            o4.x = fmaf(pu, vv.x, o4.x);
            o4.y = fmaf(pu, vv.y, o4.y);
            o4.z = fmaf(pu, vv.z, o4.z);
            o4.w = fmaf(pu, vv.w, o4.w);
        }
        o4.x *= rinv; o4.y *= rinv; o4.z *= rinv; o4.w *= rinv;

        // split-bf16 write, ic-contiguous
        uint32_t h0 = pack2bf(o4.x, o4.y);
        uint32_t h1 = pack2bf(o4.z, o4.w);
        float r0 = o4.x - __uint_as_float(h0 << 16);
        float r1 = o4.y - __uint_as_float(h0 & 0xFFFF0000u);
        float r2 = o4.z - __uint_as_float(h1 << 16);
        float r3 = o4.w - __uint_as_float(h1 & 0xFFFF0000u);
        uint32_t l0 = pack2bf(r0, r1);
        uint32_t l1 = pack2bf(r2, r3);
        size_t ob = ((size_t)((b * 256 + qrow) * 64 + t)) * 128 + lane * 4;
        *(uint2*)(avh + ob) = make_uint2(h0, h1);
        *(uint2*)(avl + ob) = make_uint2(l0, l1);
        __syncwarp();
    }
}

// ---------------------------------------------------------------------------
extern "C" void kernel_launch(void* const* d_in, const int* in_sizes, int n_in,
                              void* d_out, int out_size) {
    const float* x     = (const float*)d_in[0];
    const float* wq    = (const float*)d_in[1];
    const float* wk    = (const float*)d_in[2];
    const float* wv    = (const float*)d_in[3];
    const float* wo    = (const float*)d_in[4];
    const float* sigma = (const float*)d_in[5];
    float* out = (float*)d_out;

    float* qkv;
    __nv_bfloat16 *xh, *xl, *avh, *avl, *w1h, *w1l, *w2h, *w2l;
    cudaGetSymbolAddress((void**)&qkv, g_qkv);
    cudaGetSymbolAddress((void**)&xh,  g_xh);
    cudaGetSymbolAddress((void**)&xl,  g_xl);
    cudaGetSymbolAddress((void**)&avh, g_avh);
    cudaGetSymbolAddress((void**)&avl, g_avl);
    cudaGetSymbolAddress((void**)&w1h, g_w1h);
    cudaGetSymbolAddress((void**)&w1l, g_w1l);
    cudaGetSymbolAddress((void**)&w2h, g_w2h);
    cudaGetSymbolAddress((void**)&w2l, g_w2l);

    cudaFuncSetAttribute(split_x_k,
                         cudaFuncAttributeMaxDynamicSharedMemorySize, 66560);
    split_x_k<<<dim3(256, 8), 256, 66560>>>(x, xh, xl);

    pack_w1_k<<<(192 * 2304 + 255) / 256, 256>>>(wq, wk, wv);
    pack_w2_k<<<(256 * 1152 + 255) / 256, 256>>>(wo);

    {
        auto k = conv_mma<16, 192, false, true>;
        cudaFuncSetAttribute(k, cudaFuncAttributeMaxDynamicSharedMemorySize,
                             CONV_SMEM);
        k<<<dim3(3, 64, 8), 256, CONV_SMEM>>>(xh, xl, w1h, w1l, qkv,
                                              nullptr, nullptr);
    }

    cudaFuncSetAttribute(attn_kernel,
                         cudaFuncAttributeMaxDynamicSharedMemorySize, ATTN_SMEM);
    attn_kernel<<<dim3(T_, B_), 512, ATTN_SMEM>>>(qkv, avh, avl);

    {
        auto k = conv_mma<8, 256, true, false>;
        cudaFuncSetAttribute(k, cudaFuncAttributeMaxDynamicSharedMemorySize,
                             CONV_SMEM);
        k<<<dim3(4, 64, 8), 256, CONV_SMEM>>>(avh, avl, w2h, w2l, out,
                                              x, sigma);
    }
}

// round 5
// speedup vs baseline: 3.5216x; 1.3636x over previous
#include <cuda_runtime.h>
#include <cuda_bf16.h>
#include <cstdint>

#define B_   8
#define V_   256
#define T_   64

// ---------------------------------------------------------------------------
// Global scratch
// ---------------------------------------------------------------------------
__device__ __nv_bfloat16 g_xh[8ll * 256 * 64 * 256];     // [b][v][t][256ic]
__device__ __nv_bfloat16 g_xl[8ll * 256 * 64 * 256];
__device__ __nv_bfloat16 g_qkvh[8ll * 64 * 256 * 192];   // [b][t][v][192]
__device__ __nv_bfloat16 g_qkvl[8ll * 64 * 256 * 192];
__device__ __nv_bfloat16 g_avh[8ll * 256 * 64 * 128];    // [b][v][t][128ic]
__device__ __nv_bfloat16 g_avl[8ll * 256 * 64 * 128];
__device__ __nv_bfloat16 g_w1h[192 * 2304], g_w1l[192 * 2304];  // [oc][chunk][tap][16]
__device__ __nv_bfloat16 g_w2h[256 * 1152], g_w2l[256 * 1152];

// ---------------------------------------------------------------------------
// Helpers
// ---------------------------------------------------------------------------
__device__ __forceinline__ uint32_t smem_u32(const void* p) {
    return (uint32_t)__cvta_generic_to_shared(p);
}
__device__ __forceinline__ uint32_t pack2bf(float f0, float f1) {
    __nv_bfloat162 h = __floats2bfloat162_rn(f0, f1);   // .x=f0 (low 16)
    return *(uint32_t*)&h;
}
__device__ __forceinline__ void split2(float f0, float f1,
                                       uint32_t& hp, uint32_t& lp) {
    hp = pack2bf(f0, f1);
    float h0 = __uint_as_float(hp << 16);
    float h1 = __uint_as_float(hp & 0xFFFF0000u);
    lp = pack2bf(f0 - h0, f1 - h1);
}

#define LDMX4(r, a) \
    asm volatile("ldmatrix.sync.aligned.m8n8.x4.shared.b16 {%0,%1,%2,%3},[%4];" \
        : "=r"((r)[0]), "=r"((r)[1]), "=r"((r)[2]), "=r"((r)[3]) : "r"(a))
#define LDMX4T(r, a) \
    asm volatile("ldmatrix.sync.aligned.m8n8.x4.trans.shared.b16 {%0,%1,%2,%3},[%4];" \
        : "=r"((r)[0]), "=r"((r)[1]), "=r"((r)[2]), "=r"((r)[3]) : "r"(a))
#define LDMX2(r, a) \
    asm volatile("ldmatrix.sync.aligned.m8n8.x2.shared.b16 {%0,%1},[%2];" \
        : "=r"((r)[0]), "=r"((r)[1]) : "r"(a))
#define CP16(dst, src, sz) \
    asm volatile("cp.async.cg.shared.global [%0], [%1], 16, %2;" \
                 :: "r"(dst), "l"(src), "r"(sz) : "memory")
#define CP_COMMIT() asm volatile("cp.async.commit_group;" ::: "memory")
#define CP_WAIT(n)  asm volatile("cp.async.wait_group %0;" :: "n"(n) : "memory")

__device__ __forceinline__ void mma16816(float* c, const uint32_t* a, const uint32_t* b) {
    asm volatile(
        "mma.sync.aligned.m16n8k16.row.col.f32.bf16.bf16.f32 "
        "{%0,%1,%2,%3},{%4,%5,%6,%7},{%8,%9},{%0,%1,%2,%3};"
        : "+f"(c[0]), "+f"(c[1]), "+f"(c[2]), "+f"(c[3])
        : "r"(a[0]), "r"(a[1]), "r"(a[2]), "r"(a[3]), "r"(b[0]), "r"(b[1]));
}

// ---------------------------------------------------------------------------
// split_x: x NCHW fp32 -> [b][y][t][256ic] bf16 hi/lo
// ---------------------------------------------------------------------------
__global__ void split_x_k(const float* __restrict__ x,
                          __nv_bfloat16* __restrict__ xh,
                          __nv_bfloat16* __restrict__ xl) {
    extern __shared__ float s[];               // [256 ic][65]
    const int y = blockIdx.x, b = blockIdx.y, tid = threadIdx.x;
    for (int r = 0; r < 64; r++) {
        int idx = r * 256 + tid, ic = idx >> 6, t = idx & 63;
        s[ic * 65 + t] = x[(((size_t)b * 256 + ic) * 256 + y) * 64 + t];
    }
    __syncthreads();
    size_t ob = ((size_t)(b * 256 + y)) * 64 * 256;
    for (int r = 0; r < 32; r++) {
        int idx = r * 512 + tid * 2, t = idx >> 8, ic = idx & 255;
        float f0 = s[ic * 65 + t], f1 = s[(ic + 1) * 65 + t];
        uint32_t hp, lp;
        split2(f0, f1, hp, lp);
        *(uint32_t*)(xh + ob + (size_t)t * 256 + ic) = hp;
        *(uint32_t*)(xl + ob + (size_t)t * 256 + ic) = lp;
    }
}

// ---------------------------------------------------------------------------
// Weight packing: w[oc][ic][3][3] -> [oc][icchunk][tap][16ic] hi/lo
// ---------------------------------------------------------------------------
__global__ void pack_w1_k(const float* __restrict__ wq,
                          const float* __restrict__ wk,
                          const float* __restrict__ wv) {
    int id = blockIdx.x * blockDim.x + threadIdx.x;
    if (id >= 192 * 2304) return;
    int oc = id / 2304, kp = id % 2304;
    int chunk = kp / 144, rem = kp % 144, tap = rem / 16, i = rem & 15;
    int ic = chunk * 16 + i;
    float v;
    if (oc < 32)       v = wq[(oc * 256 + ic) * 9 + tap];
    else if (oc < 64)  v = wk[((oc - 32) * 256 + ic) * 9 + tap];
    else               v = wv[((oc - 64) * 256 + ic) * 9 + tap];
    __nv_bfloat16 h = __float2bfloat16(v);
    g_w1h[id] = h;
    g_w1l[id] = __float2bfloat16(v - __bfloat162float(h));
}

__global__ void pack_w2_k(const float* __restrict__ wo) {
    int id = blockIdx.x * blockDim.x + threadIdx.x;
    if (id >= 256 * 1152) return;
    int oc = id / 1152, kp = id % 1152;
    int chunk = kp / 144, rem = kp % 144, tap = rem / 16, i = rem & 15;
    int ic = chunk * 16 + i;
    float v = wo[(oc * 128 + ic) * 9 + tap];
    __nv_bfloat16 h = __float2bfloat16(v);
    g_w2h[id] = h;
    g_w2l[id] = __float2bfloat16(v - __bfloat162float(h));
}

// ---------------------------------------------------------------------------
// conv3x3 via mma.sync bf16 (hi/lo split, 3 passes), cp.async double-buffered.
// CTA: 512 thr (16 warps: 8 m-warps x 2 n-warps). M=512 positions
// (8 V-rows x 64 T) x N=64 oc. Chunk = 16 ic.
// Patch: [10 rows][68 cols] pixels of 48B. B: [64 oc][304B: 9 taps x 16 ic].
// ---------------------------------------------------------------------------
#define A_LO   32640
#define B_HI   65280
#define BUFSZ  104192
#define CONV_SMEM 208384

template<int ICC, int OCTOT, bool TRANS>
__global__ __launch_bounds__(512, 1)
void conv_mma(const __nv_bfloat16* __restrict__ inh,
              const __nv_bfloat16* __restrict__ inl,
              const __nv_bfloat16* __restrict__ wh,
              const __nv_bfloat16* __restrict__ wl,
              __nv_bfloat16* __restrict__ outh,
              __nv_bfloat16* __restrict__ outl,
              float* __restrict__ out32,
              const float* __restrict__ resid,
              const float* __restrict__ sigma) {
    constexpr int IC = ICC * 16;
    extern __shared__ char sm[];

    const int tid  = threadIdx.x;
    const int lane = tid & 31;
    const int w    = tid >> 5;
    const int ocB  = blockIdx.x * 64;
    const int y0   = blockIdx.y * 8;
    const int b    = blockIdx.z;
    const int m0   = (w & 7) * 64;
    const int n0   = (w >> 3) * 32;
    const uint32_t su = smem_u32(sm);

    float acc[4][4][4];
#pragma unroll
    for (int i = 0; i < 4; i++)
#pragma unroll
        for (int j = 0; j < 4; j++)
#pragma unroll
            for (int e = 0; e < 4; e++) acc[i][j][e] = 0.f;

    auto stage = [&](int c, int buf) {
        uint32_t sdu = su + buf * BUFSZ;
        // A patch: 10x66 pixels, 32B (16 ic) each, hi+lo
        for (int i = tid; i < 1320; i += 512) {
            int half = i & 1, p = i >> 1;
            int row = p / 66, col = p - row * 66;
            int gy = y0 + row - 1, gt = col - 1;
            bool ok = ((unsigned)gy < 256u) && ((unsigned)gt < 64u);
            const __nv_bfloat16* base = half ? inl : inh;
            const __nv_bfloat16* src = ok
                ? base + ((size_t)((b * 256 + gy) * 64 + gt)) * IC + c * 16
                : base;
            uint32_t dst = sdu + half * A_LO + (uint32_t)(row * 68 + col) * 48;
            int sz = ok ? 16 : 0;
            CP16(dst, src, sz);
            CP16(dst + 16, src + 8, sz);
        }
        // B: 64 oc x 144 bf16 (9 taps x 16 ic), hi+lo
        for (int i = tid; i < 2304; i += 512) {
            int half = i >= 1152;
            int r = half ? i - 1152 : i;
            int n = r / 18, seg = r - n * 18;
            const __nv_bfloat16* src = (half ? wl : wh)
                + ((size_t)(ocB + n) * ICC + c) * 144 + seg * 8;
            uint32_t dst = sdu + B_HI + half * 19456 + n * 304 + seg * 16;
            CP16(dst, src, 16);
        }
        CP_COMMIT();
    };

    stage(0, 0);

    for (int c = 0; c < ICC; ++c) {
        if (c + 1 < ICC) { stage(c + 1, (c + 1) & 1); CP_WAIT(1); }
        else             { CP_WAIT(0); }
        __syncthreads();

        const uint32_t sa = su + (c & 1) * BUFSZ;
        const uint32_t sb = sa + B_HI;
        const int l16 = lane & 15;
#pragma unroll
        for (int tap = 0; tap < 9; ++tap) {
            const int ky = tap / 3, kx = tap - ky * 3;
            uint32_t bh[4][2], bl[4][2];
#pragma unroll
            for (int nt = 0; nt < 4; ++nt) {
                uint32_t ad = sb + (n0 + nt * 8 + (l16 & 7)) * 304
                            + tap * 32 + (l16 >> 3) * 16;
                LDMX2(bh[nt], ad);
                LDMX2(bl[nt], ad + 19456);
            }
#pragma unroll
            for (int mt = 0; mt < 4; ++mt) {
                int mrow = m0 + mt * 16 + l16;
                int rp = (mrow >> 6) + ky, cp = (mrow & 63) + kx;
                uint32_t ad = sa + (uint32_t)(rp * 68 + cp) * 48 + (lane >> 4) * 16;
                uint32_t ah[4], al[4];
                LDMX4(ah, ad);
                LDMX4(al, ad + A_LO);
#pragma unroll
                for (int nt = 0; nt < 4; ++nt) {
                    mma16816(acc[mt][nt], ah, bh[nt]);
                    mma16816(acc[mt][nt], ah, bl[nt]);
                    mma16816(acc[mt][nt], al, bh[nt]);
                }
            }
        }
        __syncthreads();
    }

    // ---- epilogue ----
    const int r0l = lane >> 2, c0l = (lane & 3) * 2;
    if constexpr (TRANS) {
#pragma unroll
        for (int mt = 0; mt < 4; ++mt)
#pragma unroll
            for (int nt = 0; nt < 4; ++nt) {
                int oc = ocB + n0 + nt * 8 + c0l;
#pragma unroll
                for (int h = 0; h < 2; ++h) {
                    int m = m0 + mt * 16 + r0l + h * 8;
                    int v = y0 + (m >> 6), t = m & 63;
                    uint32_t hp, lp;
                    split2(acc[mt][nt][h * 2], acc[mt][nt][h * 2 + 1], hp, lp);
                    size_t base = ((size_t)((b * 64 + t) * 256 + v)) * OCTOT + oc;
                    *(uint32_t*)(outh + base) = hp;
                    *(uint32_t*)(outl + base) = lp;
                }
            }
    } else {
        float sg = sigma[0];
#pragma unroll
        for (int mt = 0; mt < 4; ++mt)
#pragma unroll
            for (int nt = 0; nt < 4; ++nt)
#pragma unroll
                for (int h = 0; h < 2; ++h) {
                    int m = m0 + mt * 16 + r0l + h * 8;
                    int v = y0 + (m >> 6), t = m & 63;
#pragma unroll
                    for (int e = 0; e < 2; ++e) {
                        int oc = ocB + n0 + nt * 8 + c0l + e;
                        size_t idx = (((size_t)b * OCTOT + oc) * 256 + v) * 64 + t;
                        out32[idx] = resid[idx] + sg * acc[mt][nt][h * 2 + e];
                    }
                }
    }
}

// ---------------------------------------------------------------------------
// Attention via mma.sync bf16 hi/lo (flash-style online softmax).
// One CTA per (b,t): 512 thr, 16 warps, warp owns 16 query rows.
// SMEM: Q hi/lo [256 x 80B], K hi/lo [256 x 80B], V hi/lo [256 x 272B].
// 4 key chunks of 64.  Output: split bf16 [b][v][t][128].
// ---------------------------------------------------------------------------
#define QH_O 0
#define QL_O 20480
#define KH_O 40960
#define KL_O 61440
#define VH_O 81920
#define VL_O 151552
#define ATTN_SMEM 221184

__global__ __launch_bounds__(512, 1)
void attn_kernel(const __nv_bfloat16* __restrict__ qh,
                 const __nv_bfloat16* __restrict__ ql,
                 __nv_bfloat16* __restrict__ avh,
                 __nv_bfloat16* __restrict__ avl) {
    extern __shared__ char smc[];
    const int tid  = threadIdx.x;
    const int lane = tid & 31;
    const int w    = tid >> 5;
    const int t    = blockIdx.x;
    const int b    = blockIdx.y;
    const uint32_t su = smem_u32(smc);

    // ---- load slice [256 rows][192 ch] hi+lo into Q/K/V smem ----
    const size_t sbase = ((size_t)(b * 64 + t)) * 256 * 192;
    for (int idx = tid; idx < 12288; idx += 512) {
        int half = idx >= 6144;
        int r = half ? idx - 6144 : idx;
        int row = r / 24, seg = r - row * 24;
        float4 val = *(const float4*)((half ? ql : qh) + sbase + (size_t)row * 192 + seg * 8);
        uint32_t dst;
        if (seg < 4)       dst = (half ? QL_O : QH_O) + row * 80 + seg * 16;
        else if (seg < 8)  dst = (half ? KL_O : KH_O) + row * 80 + (seg - 4) * 16;
        else               dst = (half ? VL_O : VH_O) + row * 272 + (seg - 8) * 16;
        *(float4*)(smc + dst) = val;
    }
    __syncthreads();

    const int q0  = w * 16;
    const int l16 = lane & 15;

    float o[16][4];
#pragma unroll
    for (int i = 0; i < 16; i++)
#pragma unroll
        for (int j = 0; j < 4; j++) o[i][j] = 0.f;
    float mrow[2] = {-1e30f, -1e30f};
    float lrow[2] = {0.f, 0.f};

    for (int c0 = 0; c0 < 4; ++c0) {
        // ---- S = Q K^T (chunk of 64 keys), 3-pass hi/lo ----
        float s[8][4];
#pragma unroll
        for (int i = 0; i < 8; i++)
#pragma unroll
            for (int j = 0; j < 4; j++) s[i][j] = 0.f;

#pragma unroll
        for (int kk = 0; kk < 2; ++kk) {
            uint32_t aH[4], aL[4];
            uint32_t qa = su + QH_O + (q0 + l16) * 80 + (lane >> 4) * 16 + kk * 32;
            LDMX4(aH, qa);
            LDMX4(aL, qa + (QL_O - QH_O));
#pragma unroll
            for (int ntp = 0; ntp < 4; ++ntp) {
                uint32_t kh[4], kl[4];
                uint32_t ka = su + KH_O + (c0 * 64 + ntp * 16 + l16) * 80
                            + (lane >> 4) * 16 + kk * 32;
                LDMX4(kh, ka);
                LDMX4(kl, ka + (KL_O - KH_O));
                uint32_t b0h[2] = {kh[0], kh[2]}, b1h[2] = {kh[1], kh[3]};
                uint32_t b0l[2] = {kl[0], kl[2]}, b1l[2] = {kl[1], kl[3]};
                mma16816(s[2 * ntp],     aH, b0h);
                mma16816(s[2 * ntp],     aL, b0h);
                mma16816(s[2 * ntp],     aH, b0l);
                mma16816(s[2 * ntp + 1], aH, b1h);
                mma16816(s[2 * ntp + 1], aL, b1h);
                mma16816(s[2 * ntp + 1], aH, b1l);
            }
        }

        // ---- online softmax update ----
#pragma unroll
        for (int h = 0; h < 2; ++h) {
            float mc = -1e30f;
#pragma unroll
            for (int nt = 0; nt < 8; ++nt)
                mc = fmaxf(mc, fmaxf(s[nt][2 * h], s[nt][2 * h + 1]));
            mc = fmaxf(mc, __shfl_xor_sync(0xffffffffu, mc, 1));
            mc = fmaxf(mc, __shfl_xor_sync(0xffffffffu, mc, 2));
            float mn = fmaxf(mrow[h], mc);
            float sc = __expf(mrow[h] - mn);
            mrow[h] = mn;
            float ls = 0.f;
#pragma unroll
            for (int nt = 0; nt < 8; ++nt) {
                float p0 = __expf(s[nt][2 * h] - mn);
                float p1 = __expf(s[nt][2 * h + 1] - mn);
                s[nt][2 * h] = p0; s[nt][2 * h + 1] = p1;
                ls += p0 + p1;
            }
            ls += __shfl_xor_sync(0xffffffffu, ls, 1);
            ls += __shfl_xor_sync(0xffffffffu, ls, 2);
            lrow[h] = lrow[h] * sc + ls;
#pragma unroll
            for (int nt = 0; nt < 16; ++nt) {
                o[nt][2 * h]     *= sc;
                o[nt][2 * h + 1] *= sc;
            }
        }

        // ---- O += P V (3-pass hi/lo) ----
#pragma unroll
        for (int kk = 0; kk < 4; ++kk) {
            uint32_t ph[4], pl[4];
            split2(s[2 * kk][0],     s[2 * kk][1],     ph[0], pl[0]);
            split2(s[2 * kk][2],     s[2 * kk][3],     ph[1], pl[1]);
            split2(s[2 * kk + 1][0], s[2 * kk + 1][1], ph[2], pl[2]);
            split2(s[2 * kk + 1][2], s[2 * kk + 1][3], ph[3], pl[3]);
#pragma unroll
            for (int ntp = 0; ntp < 8; ++ntp) {
                uint32_t vh[4], vl[4];
                uint32_t va = su + VH_O + (c0 * 64 + kk * 16 + l16) * 272
                            + (lane >> 4) * 16 + ntp * 32;
                LDMX4T(vh, va);
                LDMX4T(vl, va + (VL_O - VH_O));
                uint32_t bh0[2] = {vh[0], vh[1]}, bh1[2] = {vh[2], vh[3]};
                uint32_t bl0[2] = {vl[0], vl[1]}, bl1[2] = {vl[2], vl[3]};
                mma16816(o[2 * ntp],     ph, bh0);
                mma16816(o[2 * ntp],     pl, bh0);
                mma16816(o[2 * ntp],     ph, bl0);
                mma16816(o[2 * ntp + 1], ph, bh1);
                mma16816(o[2 * ntp + 1], pl, bh1);
                mma16816(o[2 * ntp + 1], ph, bl1);
            }
        }
    }

    // ---- epilogue: normalize, split bf16, store [b][v][t][128] ----
    float rin[2] = {1.f / lrow[0], 1.f / lrow[1]};
#pragma unroll
    for (int nt = 0; nt < 16; ++nt) {
        int ch = nt * 8 + (lane & 3) * 2;
#pragma unroll
        for (int h = 0; h < 2; ++h) {
            int v = q0 + (lane >> 2) + h * 8;
            float f0 = o[nt][2 * h] * rin[h];
            float f1 = o[nt][2 * h + 1] * rin[h];
            uint32_t hp, lp;
            split2(f0, f1, hp, lp);
            size_t ad = ((size_t)(b * 256 + v) * 64 + t) * 128 + ch;
            *(uint32_t*)(avh + ad) = hp;
            *(uint32_t*)(avl + ad) = lp;
        }
    }
}

// ---------------------------------------------------------------------------
extern "C" void kernel_launch(void* const* d_in, const int* in_sizes, int n_in,
                              void* d_out, int out_size) {
    const float* x     = (const float*)d_in[0];
    const float* wq    = (const float*)d_in[1];
    const float* wk    = (const float*)d_in[2];
    const float* wv    = (const float*)d_in[3];
    const float* wo    = (const float*)d_in[4];
    const float* sigma = (const float*)d_in[5];
    float* out = (float*)d_out;

    __nv_bfloat16 *xh, *xl, *qkvh, *qkvl, *avh, *avl, *w1h, *w1l, *w2h, *w2l;
    cudaGetSymbolAddress((void**)&xh,   g_xh);
    cudaGetSymbolAddress((void**)&xl,   g_xl);
    cudaGetSymbolAddress((void**)&qkvh, g_qkvh);
    cudaGetSymbolAddress((void**)&qkvl, g_qkvl);
    cudaGetSymbolAddress((void**)&avh,  g_avh);
    cudaGetSymbolAddress((void**)&avl,  g_avl);
    cudaGetSymbolAddress((void**)&w1h,  g_w1h);
    cudaGetSymbolAddress((void**)&w1l,  g_w1l);
    cudaGetSymbolAddress((void**)&w2h,  g_w2h);
    cudaGetSymbolAddress((void**)&w2l,  g_w2l);

    cudaFuncSetAttribute(split_x_k,
                         cudaFuncAttributeMaxDynamicSharedMemorySize, 66560);
    split_x_k<<<dim3(256, 8), 256, 66560>>>(x, xh, xl);

    pack_w1_k<<<(192 * 2304 + 255) / 256, 256>>>(wq, wk, wv);
    pack_w2_k<<<(256 * 1152 + 255) / 256, 256>>>(wo);

    {   // conv1: IC=256 (16 chunks), OCTOT=192, split-bf16 transposed output
        auto k = conv_mma<16, 192, true>;
        cudaFuncSetAttribute(k, cudaFuncAttributeMaxDynamicSharedMemorySize,
                             CONV_SMEM);
        k<<<dim3(3, 32, 8), 512, CONV_SMEM>>>(xh, xl, w1h, w1l,
                                              qkvh, qkvl, nullptr, nullptr, nullptr);
    }

    cudaFuncSetAttribute(attn_kernel,
                         cudaFuncAttributeMaxDynamicSharedMemorySize, ATTN_SMEM);
    attn_kernel<<<dim3(T_, B_), 512, ATTN_SMEM>>>(qkvh, qkvl, avh, avl);

    {   // conv2: IC=128 (8 chunks), OCTOT=256, fp32 out + residual
        auto k = conv_mma<8, 256, false>;
        cudaFuncSetAttribute(k, cudaFuncAttributeMaxDynamicSharedMemorySize,
                             CONV_SMEM);
        k<<<dim3(4, 32, 8), 512, CONV_SMEM>>>(avh, avl, w2h, w2l,
                                              nullptr, nullptr, out, x, sigma);
    }
}